// round 15
// baseline (speedup 1.0000x reference)
#include <cuda_runtime.h>

// Find_Ring_Bonds: B=16384 molecules, A=80 atoms, D=4 neighbors, R=10 rings, S=8.
// edges: [B, A, D] float32 (integer-valued, -1 = null neighbor)
// rings: [B, R, S] int32 (-1 = padding)
// out:   [B, A, D] float32 (1.0 iff bond (a, e[a][d]) lies in some ring)
//
// Persistent single-wave version. R12 showed three different kernels all pinned
// at 10.7us with no saturated pipe -> structural floor from n_waves=4.6
// (per-wave cold-start latency chain + wave transitions). This launches 148*6
// blocks that grid-stride over molecule groups with software-pipelined
// prefetch: next iteration's edges/rings loads are issued before the current
// iteration's barrier phases, hiding their latency entirely.
//
// Ring membership via RMW-free byte scatter (R12): each atom has a 16-byte
// staging row, flag byte per ring; plain shared byte stores (per-lane byte
// enables, no RMW hazard). Row collapsed to a 10-bit mask by movemask
// multiplies (ring bit order permuted but consistent; masks only ever ANDed).

static constexpr int A = 80;
static constexpr int D = 4;
static constexpr int R = 10;
static constexpr int S = 8;
static constexpr int MOLS_PER_BLOCK = 4;
static constexpr int THREADS = MOLS_PER_BLOCK * A;    // 320
static constexpr int BLOCKS_PER_SM = 6;
static constexpr int NUM_SMS = 148;

__global__ __launch_bounds__(THREADS, BLOCKS_PER_SM)
void find_ring_bonds_kernel(const float* __restrict__ edges,
                            const int*   __restrict__ rings,
                            float*       __restrict__ out,
                            int num_groups)                 // batch / MOLS_PER_BLOCK
{
    __shared__ uint4        staging[MOLS_PER_BLOCK][A];     // 16 flag bytes / atom
    __shared__ unsigned int atom_rings[MOLS_PER_BLOCK][A];

    const int tid = threadIdx.x;
    const int m = tid / A;          // local molecule 0..3
    const int a = tid % A;          // atom index == ring-entry index, 0..79
    const int stride = gridDim.x;

    int g = blockIdx.x;

    // Preamble prefetch for the first iteration.
    float4 e4 = make_float4(-1.f, -1.f, -1.f, -1.f);
    int ring_atom = -1;
    if (g < num_groups) {
        const long mol0 = (long)g * MOLS_PER_BLOCK + m;
        e4 = reinterpret_cast<const float4*>(edges)[mol0 * A + a];
        ring_atom = rings[mol0 * (R * S) + a];
    }

    for (; g < num_groups; g += stride) {
        const long mol = (long)g * MOLS_PER_BLOCK + m;
        const float4 cur_e = e4;
        const int cur_ra = ring_atom;

        // Issue next iteration's loads NOW; latency hides under the three
        // barrier phases below.
        const int gn = g + stride;
        if (gn < num_groups) {
            const long moln = (long)gn * MOLS_PER_BLOCK + m;
            e4 = reinterpret_cast<const float4*>(edges)[moln * A + a];
            ring_atom = rings[moln * (R * S) + a];
        }

        // Phase 0: zero own staging row (STS.128).
        staging[m][a] = make_uint4(0u, 0u, 0u, 0u);
        __syncthreads();

        // Phase 1: RMW-free byte scatter. Entry a belongs to ring r = a>>3.
        if (cur_ra >= 0)
            reinterpret_cast<char*>(&staging[m][cur_ra])[a >> 3] = 1;
        __syncthreads();

        // Phase 2: collapse own row (LDS.128) into 10-bit mask.
        const uint4 row = staging[m][a];
        const unsigned int M = 0x08040201u;
        const unsigned int my_rings = ((row.x * M) >> 24 & 0xFu)
                                    | (((row.y * M) >> 24 & 0xFu) << 4)
                                    | (((row.z * M) >> 24 & 0xFu) << 8);
        atom_rings[m][a] = my_rings;
        __syncthreads();

        // Phase 3: resolve 4 neighbor slots via shared gathers, write out.
        const int e0 = (int)cur_e.x;
        const int e1 = (int)cur_e.y;
        const int e2 = (int)cur_e.z;
        const int e3 = (int)cur_e.w;

        float4 o;
        o.x = (e0 >= 0 && (my_rings & atom_rings[m][e0])) ? 1.0f : 0.0f;
        o.y = (e1 >= 0 && (my_rings & atom_rings[m][e1])) ? 1.0f : 0.0f;
        o.z = (e2 >= 0 && (my_rings & atom_rings[m][e2])) ? 1.0f : 0.0f;
        o.w = (e3 >= 0 && (my_rings & atom_rings[m][e3])) ? 1.0f : 0.0f;

        reinterpret_cast<float4*>(out)[mol * A + a] = o;

        // No barrier needed before next Phase 0: it writes 'staging', which is
        // only read in Phase 2 (before the Phase-2 barrier of this iteration);
        // Phase 3 reads 'atom_rings', disjoint from Phase 0's writes, and the
        // Phase-0/1 barriers of the next iteration order everything else.
    }
}

extern "C" void kernel_launch(void* const* d_in, const int* in_sizes, int n_in,
                              void* d_out, int out_size)
{
    const float* edges = (const float*)d_in[0];   // [B, A, D] float32
    const int*   rings = (const int*)d_in[1];     // [B, R, S] int32
    float* out = (float*)d_out;                   // [B, A, D, 1] float32

    const int batch = out_size / (A * D);                         // 16384
    const int groups = (batch + MOLS_PER_BLOCK - 1) / MOLS_PER_BLOCK;  // 4096
    int grid = NUM_SMS * BLOCKS_PER_SM;                           // 888 (single wave)
    if (grid > groups) grid = groups;

    find_ring_bonds_kernel<<<grid, THREADS>>>(edges, rings, out, groups);
}